// round 7
// baseline (speedup 1.0000x reference)
#include <cuda_runtime.h>
#include <cuda_bf16.h>

// ============================================================================
// LigandEncoder (3-layer GIN + global_add_pool)
//   CSR gather + fully fused per-layer kernel:
//     gather(+self) -> GEMM1(bf16-split 3-pass mma.sync) -> relu
//       -> re-split in SMEM -> GEMM2 -> relu -> global
// ============================================================================

#define DIMF 128
typedef unsigned long long ull;

#define MAXN 100000
#define MAXE 1600000
#define SCAN_BS 1024

// Scratch (allocation-free rule: __device__ globals).
__device__ float g_h  [(size_t)MAXN * DIMF];
__device__ float g_h2 [(size_t)MAXN * DIMF];
__device__ int   g_deg[MAXN];
__device__ int   g_rowptr[MAXN];
__device__ int   g_cursor[MAXN];
__device__ int   g_csr[MAXE];
__device__ int   g_part[(MAXN + SCAN_BS - 1) / SCAN_BS + 1];
// per weight w: hi image 8192 b32 + lo image 8192 b32 (fragment-ordered)
__device__ __nv_bfloat16 g_wimg[6 * 32768];

// ---------------------------------------------------------------------------
// helpers
// ---------------------------------------------------------------------------
__device__ __forceinline__ unsigned smem_u32(const void* p) {
    unsigned a;
    asm("{ .reg .u64 t; cvta.to.shared.u64 t, %1; cvt.u32.u64 %0, t; }"
        : "=r"(a) : "l"(p));
    return a;
}
__device__ __forceinline__ unsigned bf2(__nv_bfloat16 a, __nv_bfloat16 b) {
    unsigned short ua = __bfloat16_as_ushort(a), ub = __bfloat16_as_ushort(b);
    return ((unsigned)ub << 16) | ua;
}
__device__ __forceinline__ ull pack2(float lo, float hi) {
    return ((ull)__float_as_uint(hi) << 32) | (ull)__float_as_uint(lo);
}
__device__ __forceinline__ void split4(float4 v, ull& hi, ull& lo) {
    __nv_bfloat16 h0 = __float2bfloat16_rn(v.x), h1 = __float2bfloat16_rn(v.y);
    __nv_bfloat16 h2 = __float2bfloat16_rn(v.z), h3 = __float2bfloat16_rn(v.w);
    __nv_bfloat16 l0 = __float2bfloat16_rn(v.x - __bfloat162float(h0));
    __nv_bfloat16 l1 = __float2bfloat16_rn(v.y - __bfloat162float(h1));
    __nv_bfloat16 l2 = __float2bfloat16_rn(v.z - __bfloat162float(h2));
    __nv_bfloat16 l3 = __float2bfloat16_rn(v.w - __bfloat162float(h3));
    hi = ((ull)bf2(h2, h3) << 32) | bf2(h0, h1);
    lo = ((ull)bf2(l2, l3) << 32) | bf2(l0, l1);
}
__device__ __forceinline__ void red_add_v4(const float* p, float4 v) {
    asm volatile("red.global.add.v4.f32 [%0], {%1,%2,%3,%4};"
                 :: "l"(p), "f"(v.x), "f"(v.y), "f"(v.z), "f"(v.w)
                 : "memory");
}
__device__ __forceinline__ void ldmatrix_x4(unsigned* f, unsigned addr) {
    asm volatile("ldmatrix.sync.aligned.m8n8.x4.shared.b16 {%0,%1,%2,%3}, [%4];"
                 : "=r"(f[0]), "=r"(f[1]), "=r"(f[2]), "=r"(f[3]) : "r"(addr));
}
__device__ __forceinline__ void lds_v2(unsigned& b0, unsigned& b1, unsigned addr) {
    asm volatile("ld.shared.v2.b32 {%0,%1}, [%2];" : "=r"(b0), "=r"(b1) : "r"(addr));
}
__device__ __forceinline__ void mma16816(float* c, const unsigned* a,
                                         unsigned b0, unsigned b1) {
    asm volatile(
        "mma.sync.aligned.m16n8k16.row.col.f32.bf16.bf16.f32 "
        "{%0,%1,%2,%3}, {%4,%5,%6,%7}, {%8,%9}, {%0,%1,%2,%3};"
        : "+f"(c[0]), "+f"(c[1]), "+f"(c[2]), "+f"(c[3])
        : "r"(a[0]), "r"(a[1]), "r"(a[2]), "r"(a[3]), "r"(b0), "r"(b1));
}
__device__ __forceinline__ void cp_async16(unsigned sdst, const void* gsrc) {
    asm volatile("cp.async.cg.shared.global [%0], [%1], 16;"
                 :: "r"(sdst), "l"(gsrc));
}

// ---------------------------------------------------------------------------
// W prep: fp32 W[k][n] -> fragment-ordered bf16 hi/lo images.
// Image b32 index: (kt*16 + nt)*64 + lane*2 + half
// ---------------------------------------------------------------------------
__global__ void wprep_kernel(const float* W0, const float* W1, const float* W2,
                             const float* W3, const float* W4, const float* W5,
                             __nv_bfloat16* out) {
    int w = blockIdx.x >> 3;
    const float* W = (w == 0) ? W0 : (w == 1) ? W1 : (w == 2) ? W2
                    : (w == 3) ? W3 : (w == 4) ? W4 : W5;
    unsigned* hi_img = (unsigned*)(out + (size_t)w * 32768);
    unsigned* lo_img = hi_img + 8192;

    int seg = blockIdx.x & 7;
#pragma unroll
    for (int it = 0; it < 4; it++) {
        int idx    = seg * 1024 + it * 256 + threadIdx.x;   // 0..8191
        int tile   = idx >> 6;
        int within = idx & 63;
        int lane   = within >> 1;
        int half   = within & 1;
        int kt = tile >> 4, nt = tile & 15;
        int k = kt * 16 + half * 8 + (lane & 3) * 2;
        int n = nt * 8 + (lane >> 2);
        float w0 = __ldg(W + (size_t)k * 128 + n);
        float w1 = __ldg(W + (size_t)(k + 1) * 128 + n);
        __nv_bfloat16 h0 = __float2bfloat16_rn(w0), h1 = __float2bfloat16_rn(w1);
        __nv_bfloat16 l0 = __float2bfloat16_rn(w0 - __bfloat162float(h0));
        __nv_bfloat16 l1 = __float2bfloat16_rn(w1 - __bfloat162float(h1));
        hi_img[idx] = bf2(h0, h1);
        lo_img[idx] = bf2(l0, l1);
    }
}

// ---------------------------------------------------------------------------
// Fused layer kernel. Block = 128 rows, 512 threads = 16 warps (4 row x 4 col).
// SMEM: A hi/lo (pitch 272) + W1 hi/lo + W2 hi/lo images.
// ---------------------------------------------------------------------------
#define A_PITCH 272u
#define SM_A_HI 0u
#define SM_A_LO 34816u
#define SM_W1   69632u       // hi 32768 then lo 32768
#define SM_W2   135168u
#define SMEM_LAYER 200704u

__global__ __launch_bounds__(512, 1)
void layer_kernel(const float* __restrict__ h,
                  const int* __restrict__ rowptr,
                  const int* __restrict__ segend,
                  const int* __restrict__ csr,
                  const __nv_bfloat16* __restrict__ w1img,
                  const float* __restrict__ b1,
                  const __nv_bfloat16* __restrict__ w2img,
                  const float* __restrict__ b2,
                  float* __restrict__ out, int M) {
    extern __shared__ char smem[];
    const unsigned sb = smem_u32(smem);
    const int tid  = threadIdx.x;
    const int lane = tid & 31;
    const int wid  = tid >> 5;
    const int wm   = wid & 3;       // row group
    const int wn   = wid >> 2;      // col group
    const int row0 = blockIdx.x * 128;

    // ---- async W image loads (overlap with gather) ----
    {
        unsigned d1 = sb + SM_W1 + tid * 16;
        const char* s1 = (const char*)w1img + tid * 16;
        unsigned d2 = sb + SM_W2 + tid * 16;
        const char* s2 = (const char*)w2img + tid * 16;
#pragma unroll
        for (int i = 0; i < 8; i++) {
            cp_async16(d1 + i * 8192, s1 + i * 8192);
            cp_async16(d2 + i * 8192, s2 + i * 8192);
        }
        asm volatile("cp.async.commit_group;");
    }

    // ---- gather phase: warp handles 8 rows, 4-way interleaved ----
#pragma unroll 1
    for (int g = 0; g < 2; g++) {
        int rbase = wid * 8 + g * 4;              // local tile row of first
        float4 sum[4];
        int s[4], len[4];
        int mx = 0;
#pragma unroll
        for (int i = 0; i < 4; i++) {
            int row = row0 + rbase + i;
            if (row < M) {
                s[i]   = __ldg(rowptr + row);
                len[i] = __ldg(segend + row) - s[i];
                sum[i] = __ldg((const float4*)(h + (size_t)row * DIMF) + lane);
            } else {
                s[i] = 0; len[i] = 0;
                sum[i] = make_float4(0.f, 0.f, 0.f, 0.f);
            }
            mx = max(mx, len[i]);
        }
#pragma unroll 1
        for (int t = 0; t < mx; t++) {
#pragma unroll
            for (int i = 0; i < 4; i++) {
                if (t < len[i]) {
                    int nb = __ldg(csr + s[i] + t);
                    float4 v = __ldg((const float4*)(h + (size_t)nb * DIMF) + lane);
                    sum[i].x += v.x; sum[i].y += v.y;
                    sum[i].z += v.z; sum[i].w += v.w;
                }
            }
        }
#pragma unroll
        for (int i = 0; i < 4; i++) {
            ull hi, lo;
            split4(sum[i], hi, lo);
            unsigned off = (rbase + i) * A_PITCH + lane * 8;
            *(ull*)(smem + SM_A_HI + off) = hi;
            *(ull*)(smem + SM_A_LO + off) = lo;
        }
    }
    asm volatile("cp.async.wait_group 0;" ::: "memory");
    __syncthreads();

    // ldmatrix lane address components
    const int arow  = lane & 15;
    const int acolb = (lane >> 4) * 16;

    float acc[2][4][4];

    // ================= GEMM1: T = relu(A @ W1 + b1) =================
#pragma unroll
    for (int i = 0; i < 2; i++)
#pragma unroll
        for (int j = 0; j < 4; j++)
#pragma unroll
            for (int q = 0; q < 4; q++) acc[i][j][q] = 0.f;

#pragma unroll
    for (int pass = 0; pass < 3; pass++) {
        const unsigned ab = sb + ((pass == 2) ? SM_A_LO : SM_A_HI);
        const unsigned bb = sb + SM_W1 + ((pass == 1) ? 32768u : 0u);
#pragma unroll
        for (int kt = 0; kt < 8; kt++) {
            unsigned fa0[4], fa1[4];
            unsigned ad = ab + (wm * 32 + arow) * A_PITCH + kt * 32 + acolb;
            ldmatrix_x4(fa0, ad);
            ldmatrix_x4(fa1, ad + 16 * A_PITCH);
#pragma unroll
            for (int j = 0; j < 4; j++) {
                int nt = wn * 4 + j;
                unsigned b0v, b1v;
                lds_v2(b0v, b1v, bb + ((kt * 16 + nt) * 64 + lane * 2) * 4);
                mma16816(acc[0][j], fa0, b0v, b1v);
                mma16816(acc[1][j], fa1, b0v, b1v);
            }
        }
    }
    __syncthreads();   // all warps done reading A before overwrite

    // write T (split bf16) back into A smem; conflict-free (bank = base+lane)
#pragma unroll
    for (int j = 0; j < 4; j++) {
        int c = (wn * 4 + j) * 8 + 2 * (lane & 3);
        ull bv = __ldg((const ull*)(b1 + c));
        float bx = __uint_as_float((unsigned)bv);
        float by = __uint_as_float((unsigned)(bv >> 32));
#pragma unroll
        for (int i = 0; i < 2; i++) {
            int mrow = wm * 32 + i * 16 + (lane >> 2);
#pragma unroll
            for (int hrow = 0; hrow < 2; hrow++) {
                float v0 = fmaxf(acc[i][j][2 * hrow + 0] + bx, 0.f);
                float v1 = fmaxf(acc[i][j][2 * hrow + 1] + by, 0.f);
                __nv_bfloat16 h0 = __float2bfloat16_rn(v0);
                __nv_bfloat16 h1 = __float2bfloat16_rn(v1);
                __nv_bfloat16 l0 = __float2bfloat16_rn(v0 - __bfloat162float(h0));
                __nv_bfloat16 l1 = __float2bfloat16_rn(v1 - __bfloat162float(h1));
                unsigned off = (mrow + hrow * 8) * A_PITCH + c * 2;
                *(unsigned*)(smem + SM_A_HI + off) = bf2(h0, h1);
                *(unsigned*)(smem + SM_A_LO + off) = bf2(l0, l1);
            }
        }
    }
    __syncthreads();

    // ================= GEMM2: out = relu(T @ W2 + b2) =================
#pragma unroll
    for (int i = 0; i < 2; i++)
#pragma unroll
        for (int j = 0; j < 4; j++)
#pragma unroll
            for (int q = 0; q < 4; q++) acc[i][j][q] = 0.f;

#pragma unroll
    for (int pass = 0; pass < 3; pass++) {
        const unsigned ab = sb + ((pass == 2) ? SM_A_LO : SM_A_HI);
        const unsigned bb = sb + SM_W2 + ((pass == 1) ? 32768u : 0u);
#pragma unroll
        for (int kt = 0; kt < 8; kt++) {
            unsigned fa0[4], fa1[4];
            unsigned ad = ab + (wm * 32 + arow) * A_PITCH + kt * 32 + acolb;
            ldmatrix_x4(fa0, ad);
            ldmatrix_x4(fa1, ad + 16 * A_PITCH);
#pragma unroll
            for (int j = 0; j < 4; j++) {
                int nt = wn * 4 + j;
                unsigned b0v, b1v;
                lds_v2(b0v, b1v, bb + ((kt * 16 + nt) * 64 + lane * 2) * 4);
                mma16816(acc[0][j], fa0, b0v, b1v);
                mma16816(acc[1][j], fa1, b0v, b1v);
            }
        }
    }

    // epilogue: + b2, relu, store
#pragma unroll
    for (int j = 0; j < 4; j++) {
        int col = (wn * 4 + j) * 8 + 2 * (lane & 3);
        ull bv = __ldg((const ull*)(b2 + col));
        float bx = __uint_as_float((unsigned)bv);
        float by = __uint_as_float((unsigned)(bv >> 32));
#pragma unroll
        for (int i = 0; i < 2; i++) {
            int r = row0 + wm * 32 + i * 16 + (lane >> 2);
            if (r < M) {
                *(ull*)(out + (size_t)r * DIMF + col) =
                    pack2(fmaxf(acc[i][j][0] + bx, 0.f),
                          fmaxf(acc[i][j][1] + by, 0.f));
            }
            if (r + 8 < M) {
                *(ull*)(out + (size_t)(r + 8) * DIMF + col) =
                    pack2(fmaxf(acc[i][j][2] + bx, 0.f),
                          fmaxf(acc[i][j][3] + by, 0.f));
            }
        }
    }
}

// ---------------------------------------------------------------------------
// CSR build kernels
// ---------------------------------------------------------------------------
__global__ void zero_int_kernel(int* __restrict__ p, int n) {
    int i = blockIdx.x * blockDim.x + threadIdx.x;
    if (i < n) p[i] = 0;
}

__global__ void hist_kernel(const int* __restrict__ dst, int* __restrict__ deg, int E) {
    int e = blockIdx.x * blockDim.x + threadIdx.x;
    if (e < E) atomicAdd(deg + __ldg(dst + e), 1);
}

__global__ void scan_block_kernel(const int* __restrict__ deg, int* __restrict__ rowptr,
                                  int* __restrict__ part, int M) {
    __shared__ int sh[SCAN_BS];
    int i = blockIdx.x * SCAN_BS + threadIdx.x;
    int v = (i < M) ? deg[i] : 0;
    sh[threadIdx.x] = v;
    __syncthreads();
#pragma unroll
    for (int off = 1; off < SCAN_BS; off <<= 1) {
        int t = (threadIdx.x >= off) ? sh[threadIdx.x - off] : 0;
        __syncthreads();
        sh[threadIdx.x] += t;
        __syncthreads();
    }
    if (i < M) rowptr[i] = sh[threadIdx.x] - v;   // exclusive
    if (threadIdx.x == SCAN_BS - 1) part[blockIdx.x] = sh[SCAN_BS - 1];
}

__global__ void scan_part_kernel(int* __restrict__ part, int nb) {
    __shared__ int sh[128];
    int t = threadIdx.x;
    int v = (t < nb) ? part[t] : 0;
    sh[t] = v;
    __syncthreads();
#pragma unroll
    for (int off = 1; off < 128; off <<= 1) {
        int u = (t >= off) ? sh[t - off] : 0;
        __syncthreads();
        sh[t] += u;
        __syncthreads();
    }
    if (t < nb) part[t] = sh[t] - v;
}

__global__ void add_off_kernel(int* __restrict__ rowptr, int* __restrict__ cursor,
                               const int* __restrict__ part, int M) {
    int i = blockIdx.x * blockDim.x + threadIdx.x;
    if (i < M) {
        int v = rowptr[i] + part[i / SCAN_BS];
        rowptr[i] = v;
        cursor[i] = v;
    }
}

__global__ void fill_kernel(const int* __restrict__ src, const int* __restrict__ dst,
                            int* __restrict__ cursor, int* __restrict__ csr, int E) {
    int e = blockIdx.x * blockDim.x + threadIdx.x;
    if (e < E) {
        int d   = __ldg(dst + e);
        int pos = atomicAdd(cursor + d, 1);
        csr[pos] = __ldg(src + e);
    }
}

// ---------------------------------------------------------------------------
// pooling
// ---------------------------------------------------------------------------
__global__ void zero_kernel(float4* __restrict__ p, int n4) {
    int i = blockIdx.x * blockDim.x + threadIdx.x;
    if (i < n4) p[i] = make_float4(0.f, 0.f, 0.f, 0.f);
}

__global__ void pool_kernel(const float* __restrict__ h,
                            const int* __restrict__ batch,
                            float* __restrict__ out, int M) {
    int idx  = blockIdx.x * blockDim.x + threadIdx.x;
    int node = idx >> 5;
    int lane = idx & 31;
    if (node >= M) return;
    int g = __ldg(batch + node);
    float4 v = __ldg(((const float4*)(h + (size_t)node * DIMF)) + lane);
    red_add_v4(out + (size_t)g * DIMF + lane * 4, v);
}

// ---------------------------------------------------------------------------
// launch
// ---------------------------------------------------------------------------
extern "C" void kernel_launch(void* const* d_in, const int* in_sizes, int n_in,
                              void* d_out, int out_size) {
    const float* x     = (const float*)d_in[0];
    const int*   ei    = (const int*)d_in[1];
    const int*   batch = (const int*)d_in[2];
    const int E = in_sizes[1] / 2;
    const int M = in_sizes[2];
    const int* src = ei;
    const int* dst = ei + E;

    void *p_h, *p_h2, *p_deg, *p_rp, *p_cur, *p_csr, *p_part, *p_wimg;
    cudaGetSymbolAddress(&p_h,    g_h);
    cudaGetSymbolAddress(&p_h2,   g_h2);
    cudaGetSymbolAddress(&p_deg,  g_deg);
    cudaGetSymbolAddress(&p_rp,   g_rowptr);
    cudaGetSymbolAddress(&p_cur,  g_cursor);
    cudaGetSymbolAddress(&p_csr,  g_csr);
    cudaGetSymbolAddress(&p_part, g_part);
    cudaGetSymbolAddress(&p_wimg, g_wimg);
    float* hA = (float*)p_h;
    float* hB = (float*)p_h2;
    int* deg    = (int*)p_deg;
    int* rowptr = (int*)p_rp;
    int* cursor = (int*)p_cur;
    int* csr    = (int*)p_csr;
    int* part   = (int*)p_part;
    __nv_bfloat16* wimg = (__nv_bfloat16*)p_wimg;

    cudaFuncSetAttribute(layer_kernel,
                         cudaFuncAttributeMaxDynamicSharedMemorySize, SMEM_LAYER);

    const int nb       = (M + SCAN_BS - 1) / SCAN_BS;
    const int eBlocks  = (E + 255) / 256;
    const int mBlocks  = (M + 255) / 256;
    const int poBlocks = (M * 32 + 255) / 256;
    const int lyBlocks = (M + 127) / 128;

    // ---- weight prep (once) ----
    wprep_kernel<<<48, 256>>>(
        (const float*)d_in[3],  (const float*)d_in[5],
        (const float*)d_in[7],  (const float*)d_in[9],
        (const float*)d_in[11], (const float*)d_in[13], wimg);

    // ---- CSR build (once) ----
    zero_int_kernel<<<mBlocks, 256>>>(deg, M);
    hist_kernel<<<eBlocks, 256>>>(dst, deg, E);
    scan_block_kernel<<<nb, SCAN_BS>>>(deg, rowptr, part, M);
    scan_part_kernel<<<1, 128>>>(part, nb);
    add_off_kernel<<<mBlocks, 256>>>(rowptr, cursor, part, M);
    fill_kernel<<<eBlocks, 256>>>(src, dst, cursor, csr, E);
    // cursor[d] now == segment end for node d

    const float* hin = x;
    float* houts[3] = {hA, hB, hA};
    for (int l = 0; l < 3; l++) {
        const __nv_bfloat16* w1img = wimg + (size_t)(2 * l)     * 32768;
        const __nv_bfloat16* w2img = wimg + (size_t)(2 * l + 1) * 32768;
        const float* b1 = (const float*)d_in[3 + 4 * l + 1];
        const float* b2 = (const float*)d_in[3 + 4 * l + 3];

        layer_kernel<<<lyBlocks, 512, SMEM_LAYER>>>(
            hin, rowptr, cursor, csr, w1img, b1, w2img, b2, houts[l], M);
        hin = houts[l];
    }

    zero_kernel<<<(out_size / 4 + 255) / 256, 256>>>((float4*)d_out, out_size / 4);
    pool_kernel<<<poBlocks, 256>>>(hin, batch, (float*)d_out, M);
}

// round 8
// speedup vs baseline: 1.4719x; 1.4719x over previous
#include <cuda_runtime.h>
#include <cuda_bf16.h>

// ============================================================================
// LigandEncoder (3-layer GIN + global_add_pool)
//   CSR gather (standalone, high-occupancy) +
//   fused MLP kernel: GEMM1(bf16-split mma.sync) -> relu -> re-split in SMEM
//                     -> GEMM2 -> relu -> global
// ============================================================================

#define DIMF 128
typedef unsigned long long ull;

#define MAXN 100000
#define MAXE 1600000
#define SCAN_BS 1024

// Scratch (allocation-free rule: __device__ globals).
__device__ float g_agg[(size_t)MAXN * DIMF];
__device__ float g_h  [(size_t)MAXN * DIMF];
__device__ int   g_deg[MAXN];
__device__ int   g_rowptr[MAXN];
__device__ int   g_cursor[MAXN];
__device__ int   g_csr[MAXE];
__device__ int   g_part[(MAXN + SCAN_BS - 1) / SCAN_BS + 1];
// per weight w: hi image 8192 b32 + lo image 8192 b32 (fragment-ordered)
__device__ __nv_bfloat16 g_wimg[6 * 32768];

// ---------------------------------------------------------------------------
// helpers
// ---------------------------------------------------------------------------
__device__ __forceinline__ unsigned smem_u32(const void* p) {
    unsigned a;
    asm("{ .reg .u64 t; cvta.to.shared.u64 t, %1; cvt.u32.u64 %0, t; }"
        : "=r"(a) : "l"(p));
    return a;
}
__device__ __forceinline__ unsigned bf2(__nv_bfloat16 a, __nv_bfloat16 b) {
    unsigned short ua = __bfloat16_as_ushort(a), ub = __bfloat16_as_ushort(b);
    return ((unsigned)ub << 16) | ua;
}
__device__ __forceinline__ ull pack2(float lo, float hi) {
    return ((ull)__float_as_uint(hi) << 32) | (ull)__float_as_uint(lo);
}
__device__ __forceinline__ void split4(float4 v, ull& hi, ull& lo) {
    __nv_bfloat16 h0 = __float2bfloat16_rn(v.x), h1 = __float2bfloat16_rn(v.y);
    __nv_bfloat16 h2 = __float2bfloat16_rn(v.z), h3 = __float2bfloat16_rn(v.w);
    __nv_bfloat16 l0 = __float2bfloat16_rn(v.x - __bfloat162float(h0));
    __nv_bfloat16 l1 = __float2bfloat16_rn(v.y - __bfloat162float(h1));
    __nv_bfloat16 l2 = __float2bfloat16_rn(v.z - __bfloat162float(h2));
    __nv_bfloat16 l3 = __float2bfloat16_rn(v.w - __bfloat162float(h3));
    hi = ((ull)bf2(h2, h3) << 32) | bf2(h0, h1);
    lo = ((ull)bf2(l2, l3) << 32) | bf2(l0, l1);
}
__device__ __forceinline__ void red_add_v4(const float* p, float4 v) {
    asm volatile("red.global.add.v4.f32 [%0], {%1,%2,%3,%4};"
                 :: "l"(p), "f"(v.x), "f"(v.y), "f"(v.z), "f"(v.w)
                 : "memory");
}
__device__ __forceinline__ void ldmatrix_x4(unsigned* f, unsigned addr) {
    asm volatile("ldmatrix.sync.aligned.m8n8.x4.shared.b16 {%0,%1,%2,%3}, [%4];"
                 : "=r"(f[0]), "=r"(f[1]), "=r"(f[2]), "=r"(f[3]) : "r"(addr));
}
__device__ __forceinline__ void lds_v2(unsigned& b0, unsigned& b1, unsigned addr) {
    asm volatile("ld.shared.v2.b32 {%0,%1}, [%2];" : "=r"(b0), "=r"(b1) : "r"(addr));
}
__device__ __forceinline__ void mma16816(float* c, const unsigned* a,
                                         unsigned b0, unsigned b1) {
    asm volatile(
        "mma.sync.aligned.m16n8k16.row.col.f32.bf16.bf16.f32 "
        "{%0,%1,%2,%3}, {%4,%5,%6,%7}, {%8,%9}, {%0,%1,%2,%3};"
        : "+f"(c[0]), "+f"(c[1]), "+f"(c[2]), "+f"(c[3])
        : "r"(a[0]), "r"(a[1]), "r"(a[2]), "r"(a[3]), "r"(b0), "r"(b1));
}
__device__ __forceinline__ void cp_async16(unsigned sdst, const void* gsrc) {
    asm volatile("cp.async.cg.shared.global [%0], [%1], 16;"
                 :: "r"(sdst), "l"(gsrc));
}

// ---------------------------------------------------------------------------
// W prep: fp32 W[k][n] -> fragment-ordered bf16 hi/lo images.
// ---------------------------------------------------------------------------
__global__ void wprep_kernel(const float* W0, const float* W1, const float* W2,
                             const float* W3, const float* W4, const float* W5,
                             __nv_bfloat16* out) {
    int w = blockIdx.x >> 3;
    const float* W = (w == 0) ? W0 : (w == 1) ? W1 : (w == 2) ? W2
                    : (w == 3) ? W3 : (w == 4) ? W4 : W5;
    unsigned* hi_img = (unsigned*)(out + (size_t)w * 32768);
    unsigned* lo_img = hi_img + 8192;

    int seg = blockIdx.x & 7;
#pragma unroll
    for (int it = 0; it < 4; it++) {
        int idx    = seg * 1024 + it * 256 + threadIdx.x;   // 0..8191
        int tile   = idx >> 6;
        int within = idx & 63;
        int lane   = within >> 1;
        int half   = within & 1;
        int kt = tile >> 4, nt = tile & 15;
        int k = kt * 16 + half * 8 + (lane & 3) * 2;
        int n = nt * 8 + (lane >> 2);
        float w0 = __ldg(W + (size_t)k * 128 + n);
        float w1 = __ldg(W + (size_t)(k + 1) * 128 + n);
        __nv_bfloat16 h0 = __float2bfloat16_rn(w0), h1 = __float2bfloat16_rn(w1);
        __nv_bfloat16 l0 = __float2bfloat16_rn(w0 - __bfloat162float(h0));
        __nv_bfloat16 l1 = __float2bfloat16_rn(w1 - __bfloat162float(h1));
        hi_img[idx] = bf2(h0, h1);
        lo_img[idx] = bf2(l0, l1);
    }
}

// ---------------------------------------------------------------------------
// Fused MLP kernel: out = relu(relu(A@W1+b1)@W2+b2).
// Block = 128 rows, 512 threads = 16 warps (4 row x 4 col), warp tile 32x32.
// ---------------------------------------------------------------------------
#define A_PITCH 272u
#define SM_A_HI 0u
#define SM_A_LO 34816u
#define SM_W1   69632u       // hi 32768 then lo 32768
#define SM_W2   135168u
#define SMEM_MLP 200704u

__global__ __launch_bounds__(512, 1)
void gemm12_kernel(const float* __restrict__ A,
                   const __nv_bfloat16* __restrict__ w1img,
                   const float* __restrict__ b1,
                   const __nv_bfloat16* __restrict__ w2img,
                   const float* __restrict__ b2,
                   float* __restrict__ out, int M) {
    extern __shared__ char smem[];
    const unsigned sb = smem_u32(smem);
    const int tid  = threadIdx.x;
    const int lane = tid & 31;
    const int wid  = tid >> 5;
    const int wm   = wid & 3;       // row group
    const int wn   = wid >> 2;      // col group
    const int row0 = blockIdx.x * 128;

    // ---- async W image loads (overlap with A staging) ----
    {
        unsigned d1 = sb + SM_W1 + tid * 16;
        const char* s1 = (const char*)w1img + tid * 16;
        unsigned d2 = sb + SM_W2 + tid * 16;
        const char* s2 = (const char*)w2img + tid * 16;
#pragma unroll
        for (int i = 0; i < 8; i++) {
            cp_async16(d1 + i * 8192, s1 + i * 8192);
            cp_async16(d2 + i * 8192, s2 + i * 8192);
        }
        asm volatile("cp.async.commit_group;");
    }

    // ---- stage + split A: 128 rows x 32 float4 ----
#pragma unroll
    for (int it = 0; it < 8; it++) {
        int f = it * 512 + tid;          // 0..4095
        int m = f >> 5;
        int q = f & 31;
        float4 v = make_float4(0.f, 0.f, 0.f, 0.f);
        if (row0 + m < M)
            v = __ldg((const float4*)(A + (size_t)(row0 + m) * DIMF + q * 4));
        ull hi, lo;
        split4(v, hi, lo);
        unsigned off = m * A_PITCH + q * 8;
        *(ull*)(smem + SM_A_HI + off) = hi;
        *(ull*)(smem + SM_A_LO + off) = lo;
    }
    asm volatile("cp.async.wait_group 0;" ::: "memory");
    __syncthreads();

    const int arow  = lane & 15;
    const int acolb = (lane >> 4) * 16;

    float acc[2][4][4];

    // ================= GEMM1: T = relu(A @ W1 + b1) =================
#pragma unroll
    for (int i = 0; i < 2; i++)
#pragma unroll
        for (int j = 0; j < 4; j++)
#pragma unroll
            for (int q = 0; q < 4; q++) acc[i][j][q] = 0.f;

#pragma unroll
    for (int pass = 0; pass < 3; pass++) {
        const unsigned ab = sb + ((pass == 2) ? SM_A_LO : SM_A_HI);
        const unsigned bb = sb + SM_W1 + ((pass == 1) ? 32768u : 0u);
#pragma unroll
        for (int kt = 0; kt < 8; kt++) {
            unsigned fa0[4], fa1[4];
            unsigned ad = ab + (wm * 32 + arow) * A_PITCH + kt * 32 + acolb;
            ldmatrix_x4(fa0, ad);
            ldmatrix_x4(fa1, ad + 16 * A_PITCH);
#pragma unroll
            for (int j = 0; j < 4; j++) {
                int nt = wn * 4 + j;
                unsigned b0v, b1v;
                lds_v2(b0v, b1v, bb + ((kt * 16 + nt) * 64 + lane * 2) * 4);
                mma16816(acc[0][j], fa0, b0v, b1v);
                mma16816(acc[1][j], fa1, b0v, b1v);
            }
        }
    }
    __syncthreads();   // all warps done reading A before overwrite

    // write T (split bf16) back into A smem
#pragma unroll
    for (int j = 0; j < 4; j++) {
        int c = (wn * 4 + j) * 8 + 2 * (lane & 3);
        ull bv = __ldg((const ull*)(b1 + c));
        float bx = __uint_as_float((unsigned)bv);
        float by = __uint_as_float((unsigned)(bv >> 32));
#pragma unroll
        for (int i = 0; i < 2; i++) {
            int mrow = wm * 32 + i * 16 + (lane >> 2);
#pragma unroll
            for (int hrow = 0; hrow < 2; hrow++) {
                float v0 = fmaxf(acc[i][j][2 * hrow + 0] + bx, 0.f);
                float v1 = fmaxf(acc[i][j][2 * hrow + 1] + by, 0.f);
                __nv_bfloat16 h0 = __float2bfloat16_rn(v0);
                __nv_bfloat16 h1 = __float2bfloat16_rn(v1);
                __nv_bfloat16 l0 = __float2bfloat16_rn(v0 - __bfloat162float(h0));
                __nv_bfloat16 l1 = __float2bfloat16_rn(v1 - __bfloat162float(h1));
                unsigned off = (mrow + hrow * 8) * A_PITCH + c * 2;
                *(unsigned*)(smem + SM_A_HI + off) = bf2(h0, h1);
                *(unsigned*)(smem + SM_A_LO + off) = bf2(l0, l1);
            }
        }
    }
    __syncthreads();

    // ================= GEMM2: out = relu(T @ W2 + b2) =================
#pragma unroll
    for (int i = 0; i < 2; i++)
#pragma unroll
        for (int j = 0; j < 4; j++)
#pragma unroll
            for (int q = 0; q < 4; q++) acc[i][j][q] = 0.f;

#pragma unroll
    for (int pass = 0; pass < 3; pass++) {
        const unsigned ab = sb + ((pass == 2) ? SM_A_LO : SM_A_HI);
        const unsigned bb = sb + SM_W2 + ((pass == 1) ? 32768u : 0u);
#pragma unroll
        for (int kt = 0; kt < 8; kt++) {
            unsigned fa0[4], fa1[4];
            unsigned ad = ab + (wm * 32 + arow) * A_PITCH + kt * 32 + acolb;
            ldmatrix_x4(fa0, ad);
            ldmatrix_x4(fa1, ad + 16 * A_PITCH);
#pragma unroll
            for (int j = 0; j < 4; j++) {
                int nt = wn * 4 + j;
                unsigned b0v, b1v;
                lds_v2(b0v, b1v, bb + ((kt * 16 + nt) * 64 + lane * 2) * 4);
                mma16816(acc[0][j], fa0, b0v, b1v);
                mma16816(acc[1][j], fa1, b0v, b1v);
            }
        }
    }

    // epilogue: + b2, relu, store
#pragma unroll
    for (int j = 0; j < 4; j++) {
        int col = (wn * 4 + j) * 8 + 2 * (lane & 3);
        ull bv = __ldg((const ull*)(b2 + col));
        float bx = __uint_as_float((unsigned)bv);
        float by = __uint_as_float((unsigned)(bv >> 32));
#pragma unroll
        for (int i = 0; i < 2; i++) {
            int r = row0 + wm * 32 + i * 16 + (lane >> 2);
            if (r < M) {
                *(ull*)(out + (size_t)r * DIMF + col) =
                    pack2(fmaxf(acc[i][j][0] + bx, 0.f),
                          fmaxf(acc[i][j][1] + by, 0.f));
            }
            if (r + 8 < M) {
                *(ull*)(out + (size_t)(r + 8) * DIMF + col) =
                    pack2(fmaxf(acc[i][j][2] + bx, 0.f),
                          fmaxf(acc[i][j][3] + by, 0.f));
            }
        }
    }
}

// ---------------------------------------------------------------------------
// CSR build kernels
// ---------------------------------------------------------------------------
__global__ void zero_int_kernel(int* __restrict__ p, int n) {
    int i = blockIdx.x * blockDim.x + threadIdx.x;
    if (i < n) p[i] = 0;
}

__global__ void hist_kernel(const int* __restrict__ dst, int* __restrict__ deg, int E) {
    int e = blockIdx.x * blockDim.x + threadIdx.x;
    if (e < E) atomicAdd(deg + __ldg(dst + e), 1);
}

__global__ void scan_block_kernel(const int* __restrict__ deg, int* __restrict__ rowptr,
                                  int* __restrict__ part, int M) {
    __shared__ int sh[SCAN_BS];
    int i = blockIdx.x * SCAN_BS + threadIdx.x;
    int v = (i < M) ? deg[i] : 0;
    sh[threadIdx.x] = v;
    __syncthreads();
#pragma unroll
    for (int off = 1; off < SCAN_BS; off <<= 1) {
        int t = (threadIdx.x >= off) ? sh[threadIdx.x - off] : 0;
        __syncthreads();
        sh[threadIdx.x] += t;
        __syncthreads();
    }
    if (i < M) rowptr[i] = sh[threadIdx.x] - v;   // exclusive
    if (threadIdx.x == SCAN_BS - 1) part[blockIdx.x] = sh[SCAN_BS - 1];
}

__global__ void scan_part_kernel(int* __restrict__ part, int nb) {
    __shared__ int sh[128];
    int t = threadIdx.x;
    int v = (t < nb) ? part[t] : 0;
    sh[t] = v;
    __syncthreads();
#pragma unroll
    for (int off = 1; off < 128; off <<= 1) {
        int u = (t >= off) ? sh[t - off] : 0;
        __syncthreads();
        sh[t] += u;
        __syncthreads();
    }
    if (t < nb) part[t] = sh[t] - v;
}

__global__ void add_off_kernel(int* __restrict__ rowptr, int* __restrict__ cursor,
                               const int* __restrict__ part, int M) {
    int i = blockIdx.x * blockDim.x + threadIdx.x;
    if (i < M) {
        int v = rowptr[i] + part[i / SCAN_BS];
        rowptr[i] = v;
        cursor[i] = v;
    }
}

__global__ void fill_kernel(const int* __restrict__ src, const int* __restrict__ dst,
                            int* __restrict__ cursor, int* __restrict__ csr, int E) {
    int e = blockIdx.x * blockDim.x + threadIdx.x;
    if (e < E) {
        int d   = __ldg(dst + e);
        int pos = atomicAdd(cursor + d, 1);
        csr[pos] = __ldg(src + e);
    }
}

// ---------------------------------------------------------------------------
// gather: one warp per dst node; agg[d] = h[d] + sum of neighbor rows
// ---------------------------------------------------------------------------
__global__ void gather_kernel(const float* __restrict__ h,
                              const int* __restrict__ rowptr,
                              const int* __restrict__ seg_end,
                              const int* __restrict__ csr,
                              float* __restrict__ agg, int M) {
    int idx  = blockIdx.x * blockDim.x + threadIdx.x;
    int node = idx >> 5;
    int lane = idx & 31;
    if (node >= M) return;
    int start = __ldg(rowptr + node);
    int end   = __ldg(seg_end + node);
    float4 sum = __ldg(((const float4*)(h + (size_t)node * DIMF)) + lane);
    for (int i = start; i < end; i++) {
        int s = __ldg(csr + i);
        float4 v = __ldg(((const float4*)(h + (size_t)s * DIMF)) + lane);
        sum.x += v.x; sum.y += v.y; sum.z += v.z; sum.w += v.w;
    }
    ((float4*)(agg + (size_t)node * DIMF))[lane] = sum;
}

// ---------------------------------------------------------------------------
// pooling
// ---------------------------------------------------------------------------
__global__ void zero_kernel(float4* __restrict__ p, int n4) {
    int i = blockIdx.x * blockDim.x + threadIdx.x;
    if (i < n4) p[i] = make_float4(0.f, 0.f, 0.f, 0.f);
}

__global__ void pool_kernel(const float* __restrict__ h,
                            const int* __restrict__ batch,
                            float* __restrict__ out, int M) {
    int idx  = blockIdx.x * blockDim.x + threadIdx.x;
    int node = idx >> 5;
    int lane = idx & 31;
    if (node >= M) return;
    int g = __ldg(batch + node);
    float4 v = __ldg(((const float4*)(h + (size_t)node * DIMF)) + lane);
    red_add_v4(out + (size_t)g * DIMF + lane * 4, v);
}

// ---------------------------------------------------------------------------
// launch
// ---------------------------------------------------------------------------
extern "C" void kernel_launch(void* const* d_in, const int* in_sizes, int n_in,
                              void* d_out, int out_size) {
    const float* x     = (const float*)d_in[0];
    const int*   ei    = (const int*)d_in[1];
    const int*   batch = (const int*)d_in[2];
    const int E = in_sizes[1] / 2;
    const int M = in_sizes[2];
    const int* src = ei;
    const int* dst = ei + E;

    void *p_agg, *p_h, *p_deg, *p_rp, *p_cur, *p_csr, *p_part, *p_wimg;
    cudaGetSymbolAddress(&p_agg,  g_agg);
    cudaGetSymbolAddress(&p_h,    g_h);
    cudaGetSymbolAddress(&p_deg,  g_deg);
    cudaGetSymbolAddress(&p_rp,   g_rowptr);
    cudaGetSymbolAddress(&p_cur,  g_cursor);
    cudaGetSymbolAddress(&p_csr,  g_csr);
    cudaGetSymbolAddress(&p_part, g_part);
    cudaGetSymbolAddress(&p_wimg, g_wimg);
    float* agg = (float*)p_agg;
    float* hbf = (float*)p_h;
    int* deg    = (int*)p_deg;
    int* rowptr = (int*)p_rp;
    int* cursor = (int*)p_cur;
    int* csr    = (int*)p_csr;
    int* part   = (int*)p_part;
    __nv_bfloat16* wimg = (__nv_bfloat16*)p_wimg;

    cudaFuncSetAttribute(gemm12_kernel,
                         cudaFuncAttributeMaxDynamicSharedMemorySize, SMEM_MLP);

    const int nb       = (M + SCAN_BS - 1) / SCAN_BS;
    const int eBlocks  = (E + 255) / 256;
    const int mBlocks  = (M + 255) / 256;
    const int gaBlocks = (M * 32 + 255) / 256;
    const int lyBlocks = (M + 127) / 128;

    // ---- weight prep (once) ----
    wprep_kernel<<<48, 256>>>(
        (const float*)d_in[3],  (const float*)d_in[5],
        (const float*)d_in[7],  (const float*)d_in[9],
        (const float*)d_in[11], (const float*)d_in[13], wimg);

    // ---- CSR build (once) ----
    zero_int_kernel<<<mBlocks, 256>>>(deg, M);
    hist_kernel<<<eBlocks, 256>>>(dst, deg, E);
    scan_block_kernel<<<nb, SCAN_BS>>>(deg, rowptr, part, M);
    scan_part_kernel<<<1, 128>>>(part, nb);
    add_off_kernel<<<mBlocks, 256>>>(rowptr, cursor, part, M);
    fill_kernel<<<eBlocks, 256>>>(src, dst, cursor, csr, E);
    // cursor[d] now == segment end for node d

    const float* hin = x;
    for (int l = 0; l < 3; l++) {
        const __nv_bfloat16* w1img = wimg + (size_t)(2 * l)     * 32768;
        const __nv_bfloat16* w2img = wimg + (size_t)(2 * l + 1) * 32768;
        const float* b1 = (const float*)d_in[3 + 4 * l + 1];
        const float* b2 = (const float*)d_in[3 + 4 * l + 3];

        gather_kernel<<<gaBlocks, 256>>>(hin, rowptr, cursor, csr, agg, M);
        gemm12_kernel<<<lyBlocks, 512, SMEM_MLP>>>(agg, w1img, b1, w2img, b2, hbf, M);
        hin = hbf;
    }

    zero_kernel<<<(out_size / 4 + 255) / 256, 256>>>((float4*)d_out, out_size / 4);
    pool_kernel<<<gaBlocks, 256>>>(hin, batch, (float*)d_out, M);
}